// round 1
// baseline (speedup 1.0000x reference)
#include <cuda_runtime.h>
#include <cstdint>

// Problem constants
#define BATCH   4
#define NF      16
#define NC      8
#define NPIX    262144            // 512*512
#define DELTA_V 0.5f
#define CMAX    100000.0f

// K1 config: 64 blocks per batch, 256 threads (8 warps: 4 feature-groups x 2 pixel-warps)
#define PB        64
#define K1_THREADS 256
#define PAIRS_PER_BLOCK 2048      // (NPIX/2)/PB
#define K1_ITERS  32              // PAIRS_PER_BLOCK / 64 pixel-threads

// K3 config
#define K3_BLOCKS  256
#define K3_THREADS 256

typedef unsigned long long u64;

// ---- scratch (device globals; fully overwritten every launch) ----
__device__ float g_part1 [BATCH][PB][NF][NC];   // per-block feature-class sums
__device__ float g_part1c[BATCH][PB][NC];       // per-block class counts
__device__ float g_means [BATCH][NF][NC];
__device__ float g_factor[BATCH];               // (sum_c 1/count) / NC
__device__ float g_part2 [BATCH * K3_BLOCKS];   // per-block pass-2 partials

// ---- packed f32x2 helpers (Blackwell) ----
__device__ __forceinline__ u64 pack2(float lo, float hi) {
    u64 r; asm("mov.b64 %0, {%1, %2};" : "=l"(r) : "f"(lo), "f"(hi)); return r;
}
__device__ __forceinline__ void unpack2(u64 v, float& lo, float& hi) {
    asm("mov.b64 {%0, %1}, %2;" : "=f"(lo), "=f"(hi) : "l"(v));
}
__device__ __forceinline__ u64 fma2(u64 a, u64 b, u64 c) {
    u64 d; asm("fma.rn.f32x2 %0, %1, %2, %3;" : "=l"(d) : "l"(a), "l"(b), "l"(c)); return d;
}
__device__ __forceinline__ u64 add2(u64 a, u64 b) {
    u64 d; asm("add.rn.f32x2 %0, %1, %2;" : "=l"(d) : "l"(a), "l"(b)); return d;
}

// ============================================================================
// K1: masked per-class sums + counts. Packed pixel-pairs in f32x2.
// Warp w: feature-group fg = w&3 (features fg*4..fg*4+3), pixel-warp pw = w>>2.
// ============================================================================
__global__ void __launch_bounds__(K1_THREADS)
k1_sums(const float* __restrict__ pred, const int* __restrict__ tgt)
{
    const int tid  = threadIdx.x;
    const int w    = tid >> 5;
    const int lane = tid & 31;
    const int fg   = w & 3;
    const int pw   = w >> 2;
    const int pl   = pw * 32 + lane;          // pixel-thread id 0..63
    const int b    = blockIdx.y;

    const float* p0 = pred + (size_t)(b * NF + fg * 4) * NPIX;
    const int*   t0 = tgt  + (size_t)b * NPIX;
    const int basePair = blockIdx.x * PAIRS_PER_BLOCK;

    u64 acc[4][NC];
    u64 cnt[NC];
#pragma unroll
    for (int f = 0; f < 4; f++)
#pragma unroll
        for (int c = 0; c < NC; c++) acc[f][c] = 0ULL;
#pragma unroll
    for (int c = 0; c < NC; c++) cnt[c] = 0ULL;

    for (int i = 0; i < K1_ITERS; i++) {
        const int pair = basePair + i * 64 + pl;
        const int n0   = pair * 2;
        const int2 g   = *(const int2*)(t0 + n0);

        u64 m[NC];
#pragma unroll
        for (int c = 0; c < NC; c++)
            m[c] = pack2(g.x == c ? 1.0f : 0.0f, g.y == c ? 1.0f : 0.0f);

#pragma unroll
        for (int f = 0; f < 4; f++) {
            const u64 v = *(const u64*)(p0 + (size_t)f * NPIX + n0);  // 2 packed floats
#pragma unroll
            for (int c = 0; c < NC; c++)
                acc[f][c] = fma2(v, m[c], acc[f][c]);
        }
        if (fg == 0) {
#pragma unroll
            for (int c = 0; c < NC; c++) cnt[c] = add2(cnt[c], m[c]);
        }
    }

    // warp butterfly reduction (deterministic)
#pragma unroll
    for (int f = 0; f < 4; f++)
#pragma unroll
        for (int c = 0; c < NC; c++)
            for (int o = 16; o > 0; o >>= 1)
                acc[f][c] = add2(acc[f][c], __shfl_xor_sync(0xffffffffu, acc[f][c], o));
    if (fg == 0) {
#pragma unroll
        for (int c = 0; c < NC; c++)
            for (int o = 16; o > 0; o >>= 1)
                cnt[c] = add2(cnt[c], __shfl_xor_sync(0xffffffffu, cnt[c], o));
    }

    __shared__ float s_s[4][2][4][NC];
    __shared__ float s_c[2][NC];
    if (lane == 0) {
#pragma unroll
        for (int f = 0; f < 4; f++)
#pragma unroll
            for (int c = 0; c < NC; c++) {
                float lo, hi; unpack2(acc[f][c], lo, hi);
                s_s[fg][pw][f][c] = lo + hi;
            }
        if (fg == 0) {
#pragma unroll
            for (int c = 0; c < NC; c++) {
                float lo, hi; unpack2(cnt[c], lo, hi);
                s_c[pw][c] = lo + hi;
            }
        }
    }
    __syncthreads();

    if (tid < 128) {
        const int fg2 = tid >> 5, f2 = (tid >> 3) & 3, c2 = tid & 7;
        g_part1[b][blockIdx.x][fg2 * 4 + f2][c2] =
            s_s[fg2][0][f2][c2] + s_s[fg2][1][f2][c2];
    }
    if (tid < NC)
        g_part1c[b][blockIdx.x][tid] = s_c[0][tid] + s_c[1][tid];
}

// ============================================================================
// K2: reduce per-block partials -> means, counts, factor. 1 block, 512 threads.
// ============================================================================
__global__ void k2_finalize_means()
{
    const int t = threadIdx.x;                 // 512 = 4*16*8
    const int b = t >> 7, f = (t >> 3) & 15, c = t & 7;

    __shared__ float s_cnt[BATCH][NC];
    if (f == 0) {
        float s = 0.f;
        for (int x = 0; x < PB; x++) s += g_part1c[b][x][c];
        s_cnt[b][c] = s;
    }
    __syncthreads();

    float s = 0.f;
    for (int x = 0; x < PB; x++) s += g_part1[b][x][f][c];
    g_means[b][f][c] = s / s_cnt[b][c];

    if (t < BATCH) {
        float fs = 0.f;
        for (int c2 = 0; c2 < NC; c2++) fs += 1.0f / s_cnt[t][c2];
        g_factor[t] = fs * (1.0f / NC);
    }
}

// ============================================================================
// K3: per-pixel variance-loss term. Each thread: one quad of pixels (float4).
// ============================================================================
__global__ void __launch_bounds__(K3_THREADS)
k3_dist(const float* __restrict__ pred, const int* __restrict__ tgt)
{
    __shared__ float sm[NF * NC];
    __shared__ float s_red[8];
    const int b   = blockIdx.y;
    const int tid = threadIdx.x;

    if (tid < NF * NC)
        sm[tid] = ((const float*)g_means)[b * NF * NC + tid];
    __syncthreads();

    const int qid = blockIdx.x * K3_THREADS + tid;
    const int n0  = qid * 4;
    const int4 g  = *(const int4*)(tgt + (size_t)b * NPIX + n0);

    float m0[NF], m1[NF], m2[NF], m3[NF];
#pragma unroll
    for (int f = 0; f < NF; f++) {
        m0[f] = sm[f * NC + g.x];
        m1[f] = sm[f * NC + g.y];
        m2[f] = sm[f * NC + g.z];
        m3[f] = sm[f * NC + g.w];
    }

    float sq0 = 0.f, sq1 = 0.f, sq2 = 0.f, sq3 = 0.f;
    const float* p0 = pred + (size_t)b * NF * NPIX + n0;
#pragma unroll
    for (int f = 0; f < NF; f++) {
        const float4 v = *(const float4*)(p0 + (size_t)f * NPIX);
        float d;
        d = m0[f] - v.x; sq0 += d * d;
        d = m1[f] - v.y; sq1 += d * d;
        d = m2[f] - v.z; sq2 += d * d;
        d = m3[f] - v.w; sq3 += d * d;
    }

    float local = 0.f;
    {
        float dd, tt;
        dd = sqrtf(sq0); tt = fminf(fmaxf(dd - DELTA_V, 0.f), CMAX); local += tt * tt;
        dd = sqrtf(sq1); tt = fminf(fmaxf(dd - DELTA_V, 0.f), CMAX); local += tt * tt;
        dd = sqrtf(sq2); tt = fminf(fmaxf(dd - DELTA_V, 0.f), CMAX); local += tt * tt;
        dd = sqrtf(sq3); tt = fminf(fmaxf(dd - DELTA_V, 0.f), CMAX); local += tt * tt;
    }

    for (int o = 16; o > 0; o >>= 1)
        local += __shfl_xor_sync(0xffffffffu, local, o);
    if ((tid & 31) == 0) s_red[tid >> 5] = local;
    __syncthreads();
    if (tid < 32) {
        float v = (tid < 8) ? s_red[tid] : 0.f;
        for (int o = 16; o > 0; o >>= 1)
            v += __shfl_xor_sync(0xffffffffu, v, o);
        if (tid == 0)
            g_part2[b * gridDim.x + blockIdx.x] = v * g_factor[b];
    }
}

// ============================================================================
// K4: final deterministic reduction of BATCH*K3_BLOCKS = 1024 partials.
// ============================================================================
__global__ void k4_final(float* __restrict__ out)
{
    const int tid = threadIdx.x;               // 1024
    float v = g_part2[tid];
    __shared__ float sr[32];
    for (int o = 16; o > 0; o >>= 1)
        v += __shfl_xor_sync(0xffffffffu, v, o);
    if ((tid & 31) == 0) sr[tid >> 5] = v;
    __syncthreads();
    if (tid < 32) {
        float x = sr[tid];
        for (int o = 16; o > 0; o >>= 1)
            x += __shfl_xor_sync(0xffffffffu, x, o);
        if (tid == 0) out[0] = x;
    }
}

// ============================================================================
extern "C" void kernel_launch(void* const* d_in, const int* in_sizes, int n_in,
                              void* d_out, int out_size)
{
    const float* pred = (const float*)d_in[0];
    const int*   tgt  = (const int*)d_in[1];
    float* out = (float*)d_out;

    k1_sums<<<dim3(PB, BATCH), K1_THREADS>>>(pred, tgt);
    k2_finalize_means<<<1, 512>>>();
    k3_dist<<<dim3(K3_BLOCKS, BATCH), K3_THREADS>>>(pred, tgt);
    k4_final<<<1, 1024>>>(out);
}